// round 5
// baseline (speedup 1.0000x reference)
#include <cuda_runtime.h>
#include <cuda_bf16.h>
#include <cooperative_groups.h>
#include <math.h>
#include <cstdint>

namespace cg = cooperative_groups;

// Problem constants
#define S_LEN 4096
#define E_DIM 300
#define H_DIM 256
#define L_CH 32
#define NC 64
#define CE 25
#define CO 25
#define T_TAGS 12
#define START_TAG 10
#define STOP_TAG 11
#define EIN 325          // E + CO
#define G4H 1024         // 4*H
#define CRF_CHUNK 32
#define CRF_NCHUNK (S_LEN / CRF_CHUNK)   // 128

// padded h buffer: byteoff(f) = 4f + 16*(f>>6); 256 floats -> 1072 B, round 1088
#define HBUF_BYTES 1088

// ---------------- scratch (static device memory; no allocation) --------------
__device__ float g_embeds[S_LEN * EIN];
__device__ float g_X[2][S_LEN * G4H];
__device__ float g_hs[S_LEN * 2 * H_DIM];
__device__ float g_feats[S_LEN * T_TAGS];
__device__ float g_chunkM[CRF_NCHUNK * T_TAGS * T_TAGS];

// ---------------- small PTX helpers ------------------------------------------
__device__ __forceinline__ uint32_t s2u(const void* p) {
    uint32_t a;
    asm("{ .reg .u64 t; cvta.to.shared.u64 t, %1; cvt.u32.u64 %0, t; }"
        : "=r"(a) : "l"(p));
    return a;
}
__device__ __forceinline__ uint32_t mapa_rank(uint32_t a, uint32_t rk) {
    uint32_t d;
    asm("mapa.shared::cluster.u32 %0, %1, %2;" : "=r"(d) : "r"(a), "r"(rk));
    return d;
}
__device__ __forceinline__ void mbar_init(uint32_t a, uint32_t cnt) {
    asm volatile("mbarrier.init.shared.b64 [%0], %1;" :: "r"(a), "r"(cnt) : "memory");
}
__device__ __forceinline__ void mbar_expect(uint32_t a, uint32_t bytes) {
    asm volatile("mbarrier.arrive.expect_tx.shared.b64 _, [%0], %1;"
                 :: "r"(a), "r"(bytes) : "memory");
}
// CTA-scope acquire: st.async data lands in OUR smem, ordered by the local
// mbarrier tx-complete; cluster-scope acquire would emit CCTL.IVALL per poll.
__device__ __forceinline__ void mbar_wait(uint32_t a, uint32_t parity) {
    asm volatile(
        "{\n\t"
        ".reg .pred P;\n\t"
        "W_%=:\n\t"
        "mbarrier.try_wait.parity.acquire.cta.shared::cta.b64 P, [%0], %1, 0x989680;\n\t"
        "@!P bra W_%=;\n\t"
        "}"
        :: "r"(a), "r"(parity) : "memory");
}
__device__ __forceinline__ void st_async_u32(uint32_t dst, uint32_t val, uint32_t mbar) {
    asm volatile(
        "st.async.shared::cluster.mbarrier::complete_tx::bytes.u32 [%0], %1, [%2];"
        :: "r"(dst), "r"(val), "r"(mbar) : "memory");
}
__device__ __forceinline__ void fma2(unsigned long long& d,
                                     unsigned long long a, unsigned long long b) {
    asm("fma.rn.f32x2 %0, %1, %2, %0;" : "+l"(d) : "l"(a), "l"(b));
}
__device__ __forceinline__ float sum2(unsigned long long v) {
    return __uint_as_float((uint32_t)v) + __uint_as_float((uint32_t)(v >> 32));
}
__device__ __forceinline__ float fsig(float x) {
    return __fdividef(1.f, 1.f + __expf(-x));
}
__device__ __forceinline__ float ftanh(float x) {
    return 1.f - __fdividef(2.f, __expf(2.f * x) + 1.f);
}

// =============================================================================
// K1: char CNN + word-embedding gather -> g_embeds
// =============================================================================
__global__ void k_embed(const int* __restrict__ sentence,
                        const int* __restrict__ chars,
                        const float* __restrict__ word_embed,
                        const float* __restrict__ char_embed,
                        const float* __restrict__ conv_w,
                        const float* __restrict__ conv_b)
{
    int s = blockIdx.x;
    int tid = threadIdx.x;                 // 256 threads

    __shared__ float ce[36 * CE];
    __shared__ float swc[CO * 75];
    __shared__ float swb[CO];
    __shared__ float cv[CO * 34];

    for (int i = tid; i < 36 * CE; i += 256) ce[i] = 0.f;
    for (int i = tid; i < CO * 75; i += 256) swc[i] = conv_w[i];
    if (tid < CO) swb[tid] = conv_b[tid];
    __syncthreads();

    for (int i = tid; i < L_CH * CE; i += 256) {
        int l = i / CE, c = i % CE;
        ce[(l + 2) * CE + c] = char_embed[chars[s * L_CH + l] * CE + c];
    }
    __syncthreads();

    for (int i = tid; i < CO * 34; i += 256) {
        int o = i / 34, tpos = i % 34;
        float acc = swb[o];
        #pragma unroll
        for (int kh = 0; kh < 3; kh++) {
            const float* cer = &ce[(tpos + kh) * CE];
            const float* wr  = &swc[o * 75 + kh * CE];
            #pragma unroll
            for (int c = 0; c < CE; c++) acc = fmaf(cer[c], wr[c], acc);
        }
        cv[o * 34 + tpos] = acc;
    }
    __syncthreads();

    const float* we = word_embed + (size_t)sentence[s] * E_DIM;
    float* erow = g_embeds + (size_t)s * EIN;
    for (int i = tid; i < E_DIM; i += 256) erow[i] = we[i];

    if (tid < CO) {
        float m = cv[tid * 34];
        #pragma unroll
        for (int t = 1; t < 34; t++) m = fmaxf(m, cv[tid * 34 + t]);
        erow[E_DIM + tid] = m;
    }
}

// =============================================================================
// K2: X[d] = embeds @ Wih_d^T + b_d     ([4096,325] x [325,1024])
// =============================================================================
__global__ void k_gemm(const float* __restrict__ Wf, const float* __restrict__ bf,
                       const float* __restrict__ Wb, const float* __restrict__ bb)
{
    int d = blockIdx.z;
    const float* W    = d ? Wb : Wf;
    const float* bias = d ? bb : bf;
    float* X = g_X[d];
    const float* A = g_embeds;

    int m0 = blockIdx.y * 64;
    int n0 = blockIdx.x * 64;

    __shared__ float As[16][65];
    __shared__ float Bs[16][65];

    int tx = threadIdx.x & 15;
    int ty = threadIdx.x >> 4;

    float c[4][4] = {};

    for (int k0 = 0; k0 < EIN; k0 += 16) {
        #pragma unroll
        for (int l = 0; l < 4; l++) {
            int idx = threadIdx.x + l * 256;
            int kk = idx & 15, ml = idx >> 4;
            int k = k0 + kk;
            As[kk][ml] = (k < EIN) ? A[(size_t)(m0 + ml) * EIN + k] : 0.f;
            Bs[kk][ml] = (k < EIN) ? W[(size_t)(n0 + ml) * EIN + k] : 0.f;
        }
        __syncthreads();
        #pragma unroll
        for (int kk = 0; kk < 16; kk++) {
            float a[4], b[4];
            #pragma unroll
            for (int i = 0; i < 4; i++) a[i] = As[kk][ty + 16 * i];
            #pragma unroll
            for (int j = 0; j < 4; j++) b[j] = Bs[kk][tx + 16 * j];
            #pragma unroll
            for (int i = 0; i < 4; i++)
                #pragma unroll
                for (int j = 0; j < 4; j++)
                    c[i][j] = fmaf(a[i], b[j], c[i][j]);
        }
        __syncthreads();
    }

    #pragma unroll
    for (int i = 0; i < 4; i++) {
        int m = m0 + ty + 16 * i;
        #pragma unroll
        for (int j = 0; j < 4; j++) {
            int n = n0 + tx + 16 * j;
            X[(size_t)m * G4H + n] = c[i][j] + bias[n];
        }
    }
}

// =============================================================================
// K3: BiLSTM recurrence, warp-autonomous (NO __syncthreads in the loop).
// Template NR = cluster size (8 or 16). CTA rank r owns EPC=256/NR h-elements.
// Warp w owns EPW=EPC/8 elements = RPW=4*EPW gate rows. Lane layout:
//   row_id = lane & (RPW-1), qpart = lane >> log2(RPW)
//   row: gate g = row_id/EPW, elem er = row_id%EPW
//   cols [qpart*CPL, qpart*CPL+CPL), CPL = 256/LPR, LPR = 32/RPW
// Reduce via shfl.bfly (xor RPW, 2*RPW...). Lanes < EPW compute gates, keep
// cstate, write g_hs. Fan-out: lane L sends elem L/NR to rank L%NR via one
// st.async into the padded double-buffered h (16B pad per 64 floats, so the
// per-warp multi-quarter LDS.128 hits distinct 16B banks).
// Buffer-reuse safety: every lane's LDS of phase s feeds (via bfly/shuffles)
// the h value it sends for phase s+1; deliveries for phase s+2 transitively
// require all phase-s+1 sends, hence all phase-s reads everywhere.
// =============================================================================
template<int NR>
__global__ void __launch_bounds__(256, 1)
k_lstm_t(const float* __restrict__ Whh_f, const float* __restrict__ Whh_b)
{
    constexpr int EPC = 256 / NR;      // elems per CTA
    constexpr int EPW = EPC / 8;       // elems per warp
    constexpr int RPW = 4 * EPW;       // rows per warp
    constexpr int LPR = 32 / RPW;      // lanes per row
    constexpr int CPL = 256 / LPR;     // cols per lane
    constexpr int NQ  = CPL / 64;      // 64-col sub-quarters per lane

    cg::cluster_group cluster = cg::this_cluster();
    int r = cluster.block_rank();      // 0..NR-1
    int d = blockIdx.x / NR;           // direction

    __shared__ __align__(16) char shbuf[2 * HBUF_BYTES];
    __shared__ __align__(8) unsigned long long mbar[2];

    int t     = threadIdx.x;
    int wid   = t >> 5;
    int lane  = t & 31;
    int row_id = lane & (RPW - 1);
    int qpart  = lane / RPW;
    int g  = row_id / EPW;
    int er = row_id % EPW;

    uint32_t sh_u = s2u(shbuf);
    uint32_t mb_u = s2u(mbar);

    for (int i = t; i < 2 * HBUF_BYTES / 4; i += 256)
        reinterpret_cast<float*>(shbuf)[i] = 0.f;
    if (t == 0) {
        mbar_init(mb_u + 0, 1);
        mbar_init(mb_u + 8, 1);
    }
    __syncthreads();
    if (t == 0) {
        mbar_expect(mb_u + 8, 1024);   // phase 1
        mbar_expect(mb_u + 0, 1024);   // phase 2
    }
    __syncthreads();
    cluster.sync();

    uint32_t rsh[NR], rmb[NR];
    #pragma unroll
    for (int rk = 0; rk < NR; rk++) {
        rsh[rk] = mapa_rank(sh_u, rk);
        rmb[rk] = mapa_rank(mb_u, rk);
    }

    // weights: row = g*256 + EPC*r + wid*EPW + er, cols qpart*CPL..+CPL
    const float* Whh = d ? Whh_b : Whh_f;
    int grow = g * 256 + EPC * r + wid * EPW + er;
    ulonglong2 wreg[NQ * 16];
    #pragma unroll
    for (int sq = 0; sq < NQ; sq++) {
        const ulonglong2* wsrc = reinterpret_cast<const ulonglong2*>(
            Whh + (size_t)grow * 256 + qpart * CPL + sq * 64);
        #pragma unroll
        for (int i = 0; i < 16; i++) wreg[sq * 16 + i] = wsrc[i];
    }

    const float* Xd = g_X[d];
    int tt = d ? (S_LEN - 1) : 0;
    int ds = d ? -1 : 1;
    float xcur = (qpart == 0) ? Xd[(size_t)tt * G4H + grow] : 0.f;

    float cstate = 0.f;
    int p = 0;
    int par0 = 0, par1 = 0;
    int el = lane / NR;                // element this lane ships
    int rk = lane % NR;                // destination rank
    int fglob = EPC * r + wid * EPW + el;
    uint32_t doff_base = (uint32_t)(4 * fglob + 16 * (fglob >> 6));
    int hsrow = EPC * r + wid * EPW + lane;   // g_hs index for lanes < EPW

    for (int s = 0; s < S_LEN; s++) {
        if (s > 0) {
            int b = s & 1;
            if (b) { mbar_wait(mb_u + 8, par1); par1 ^= 1; }
            else   { mbar_wait(mb_u + 0, par0); par0 ^= 1; }
            if (t == 0 && s + 2 < S_LEN) mbar_expect(mb_u + b * 8, 1024);
        }

        float xnext = (qpart == 0 && s + 1 < S_LEN)
                        ? Xd[(size_t)(tt + ds) * G4H + grow] : 0.f;

        // partial dot over this lane's cols (padded sub-quarters of 272 B)
        unsigned long long a0 = 0ull, a1 = 0ull, a2 = 0ull, a3 = 0ull;
        const char* hb = shbuf + p * HBUF_BYTES + qpart * NQ * 272;
        #pragma unroll
        for (int sq = 0; sq < NQ; sq++) {
            const ulonglong2* hv = reinterpret_cast<const ulonglong2*>(hb + sq * 272);
            #pragma unroll
            for (int i = 0; i < 16; i += 2) {
                ulonglong2 h2 = hv[i];
                ulonglong2 h3 = hv[i + 1];
                fma2(a0, wreg[sq * 16 + i].x, h2.x);
                fma2(a1, wreg[sq * 16 + i].y, h2.y);
                fma2(a2, wreg[sq * 16 + i + 1].x, h3.x);
                fma2(a3, wreg[sq * 16 + i + 1].y, h3.y);
            }
        }
        float dot = (sum2(a0) + sum2(a1)) + (sum2(a2) + sum2(a3)) + xcur;

        // reduce across qparts (lanes differing in bits >= log2(RPW))
        #pragma unroll
        for (int m = RPW; m < 32; m <<= 1)
            dot += __shfl_xor_sync(0xffffffffu, dot, m);

        // gather the 4 gate rows for element (lane % EPW)
        int ee = lane & (EPW - 1);
        float zi = __shfl_sync(0xffffffffu, dot, 0 * EPW + ee);
        float zf = __shfl_sync(0xffffffffu, dot, 1 * EPW + ee);
        float zg = __shfl_sync(0xffffffffu, dot, 2 * EPW + ee);
        float zo = __shfl_sync(0xffffffffu, dot, 3 * EPW + ee);

        float h = 0.f;
        if (lane < EPW) {
            float ig = fsig(zi);
            float fg = fsig(zf);
            float og = fsig(zo);
            float gg = ftanh(zg);
            cstate = fg * cstate + ig * gg;
            h = og * ftanh(cstate);
            g_hs[(size_t)tt * (2 * H_DIM) + d * H_DIM + hsrow] = h;
        }

        if (s + 1 < S_LEN) {
            float hv2 = __shfl_sync(0xffffffffu, h, el);
            uint32_t off   = (uint32_t)((p ^ 1) * HBUF_BYTES) + doff_base;
            uint32_t mboff = ((s + 1) & 1) * 8;
            st_async_u32(rsh[rk] + off, __float_as_uint(hv2), rmb[rk] + mboff);
        }

        p ^= 1;
        tt += ds;
        xcur = xnext;
    }

    cluster.sync();
}

// =============================================================================
// K4: feats = lstm_out @ W_tag^T + b_tag
// =============================================================================
__global__ void k_feats(const float* __restrict__ W_tag, const float* __restrict__ b_tag)
{
    int s = blockIdx.x;
    int w = threadIdx.x >> 5;
    int lane = threadIdx.x & 31;
    if (w >= T_TAGS) return;

    const float* hrow = g_hs + (size_t)s * (2 * H_DIM);
    const float* wt = W_tag + (size_t)w * (2 * H_DIM);
    float acc = 0.f;
    #pragma unroll 4
    for (int k = lane; k < 2 * H_DIM; k += 32) acc = fmaf(hrow[k], wt[k], acc);
    #pragma unroll
    for (int off = 16; off; off >>= 1) acc += __shfl_down_sync(0xffffffffu, acc, off);
    if (lane == 0) g_feats[s * T_TAGS + w] = acc + b_tag[w];
}

// =============================================================================
// K5a: CRF parallel scan, stage 1.
// =============================================================================
__global__ void k_crf1(const float* __restrict__ trans)
{
    int b = blockIdx.x;
    int tid = threadIdx.x;                 // 144
    int i = tid / T_TAGS, k = tid % T_TAGS;

    __shared__ float cur[T_TAGS][T_TAGS + 1];
    __shared__ float str[T_TAGS * T_TAGS];

    str[tid] = trans[tid];
    __syncthreads();

    float trk[T_TAGS];
    #pragma unroll
    for (int j = 0; j < T_TAGS; j++) trk[j] = str[j * T_TAGS + k];

    int s0 = b * CRF_CHUNK;
    cur[i][k] = str[i * T_TAGS + k] + g_feats[s0 * T_TAGS + k];
    __syncthreads();

    float featn = g_feats[(s0 + 1) * T_TAGS + k];
    for (int s = s0 + 1; s < s0 + CRF_CHUNK; s++) {
        float fcur = featn;
        featn = (s + 1 < s0 + CRF_CHUNK) ? g_feats[(s + 1) * T_TAGS + k] : 0.f;

        float av[T_TAGS];
        float m = -1e30f;
        #pragma unroll
        for (int j = 0; j < T_TAGS; j++) {
            av[j] = cur[i][j] + trk[j];
            m = fmaxf(m, av[j]);
        }
        float sum = 0.f;
        #pragma unroll
        for (int j = 0; j < T_TAGS; j++) sum += __expf(av[j] - m);
        float nv = fcur + m + __logf(sum);
        __syncthreads();
        cur[i][k] = nv;
        __syncthreads();
    }
    g_chunkM[b * 144 + i * T_TAGS + k] = cur[i][k];
}

// =============================================================================
// K5b: CRF stage 2 — fold chunk matrices, terminal LSE, gold.
// =============================================================================
__global__ void k_crf2(const float* __restrict__ trans,
                       const int* __restrict__ tags,
                       float* __restrict__ out)
{
    int lane = threadIdx.x;                // 32 threads
    int j = (lane < T_TAGS) ? lane : 0;

    float alpha = (lane == START_TAG) ? 0.f : -10000.f;

    for (int b = 0; b < CRF_NCHUNK; b++) {
        const float* M = g_chunkM + b * 144;
        float mv[T_TAGS];
        #pragma unroll
        for (int i = 0; i < T_TAGS; i++) mv[i] = M[i * T_TAGS + j];
        float av[T_TAGS];
        float m = -1e30f;
        #pragma unroll
        for (int i = 0; i < T_TAGS; i++) {
            av[i] = __shfl_sync(0xffffffffu, alpha, i) + mv[i];
            m = fmaxf(m, av[i]);
        }
        float sum = 0.f;
        #pragma unroll
        for (int i = 0; i < T_TAGS; i++) sum += __expf(av[i] - m);
        alpha = m + __logf(sum);
    }

    float term = alpha + trans[j * T_TAGS + STOP_TAG];
    float m = -1e30f;
    #pragma unroll
    for (int i = 0; i < T_TAGS; i++)
        m = fmaxf(m, __shfl_sync(0xffffffffu, term, i));
    float sum = 0.f;
    #pragma unroll
    for (int i = 0; i < T_TAGS; i++)
        sum += __expf(__shfl_sync(0xffffffffu, term, i) - m);
    float fwd = m + __logf(sum);

    float g = 0.f;
    for (int s = lane; s < S_LEN; s += 32) {
        int tcur = tags[s];
        int tprev = s ? tags[s - 1] : START_TAG;
        g += trans[tprev * T_TAGS + tcur] + g_feats[s * T_TAGS + tcur];
    }
    #pragma unroll
    for (int off = 16; off; off >>= 1) g += __shfl_down_sync(0xffffffffu, g, off);

    if (lane == 0) {
        g += trans[tags[S_LEN - 1] * T_TAGS + STOP_TAG];
        out[0] = fwd - g;
    }
}

// =============================================================================
// launch
// =============================================================================
extern "C" void kernel_launch(void* const* d_in, const int* in_sizes, int n_in,
                              void* d_out, int out_size)
{
    const int*   sentence   = (const int*)  d_in[0];
    const int*   chars      = (const int*)  d_in[1];
    const int*   tags       = (const int*)  d_in[2];
    const float* word_embed = (const float*)d_in[4];
    const float* char_embed = (const float*)d_in[5];
    const float* conv_w     = (const float*)d_in[6];
    const float* conv_b     = (const float*)d_in[7];
    const float* Wih_f      = (const float*)d_in[8];
    const float* Whh_f      = (const float*)d_in[9];
    const float* b_f        = (const float*)d_in[10];
    const float* Wih_b      = (const float*)d_in[11];
    const float* Whh_b      = (const float*)d_in[12];
    const float* b_b        = (const float*)d_in[13];
    const float* W_tag      = (const float*)d_in[14];
    const float* b_tag      = (const float*)d_in[15];
    const float* trans      = (const float*)d_in[16];
    float* out = (float*)d_out;

    k_embed<<<S_LEN, 256>>>(sentence, chars, word_embed, char_embed, conv_w, conv_b);
    k_gemm<<<dim3(G4H / 64, S_LEN / 64, 2), 256>>>(Wih_f, b_f, Wih_b, b_b);

    // Prefer cluster-16 (non-portable); fall back to cluster-8.
    bool done = false;
    {
        cudaFuncSetAttribute(k_lstm_t<16>,
                             cudaFuncAttributeNonPortableClusterSizeAllowed, 1);
        cudaLaunchConfig_t cfg = {};
        cfg.gridDim  = dim3(32, 1, 1);
        cfg.blockDim = dim3(256, 1, 1);
        cudaLaunchAttribute at[1];
        at[0].id = cudaLaunchAttributeClusterDimension;
        at[0].val.clusterDim.x = 16;
        at[0].val.clusterDim.y = 1;
        at[0].val.clusterDim.z = 1;
        cfg.attrs = at;
        cfg.numAttrs = 1;
        int nclus = 0;
        cudaError_t qe = cudaOccupancyMaxActiveClusters(&nclus, k_lstm_t<16>, &cfg);
        if (qe == cudaSuccess && nclus >= 2) {
            cudaError_t le = cudaLaunchKernelEx(&cfg, k_lstm_t<16>, Whh_f, Whh_b);
            done = (le == cudaSuccess);
        }
        if (!done) cudaGetLastError();
    }
    if (!done) {
        cudaLaunchConfig_t cfg = {};
        cfg.gridDim  = dim3(16, 1, 1);
        cfg.blockDim = dim3(256, 1, 1);
        cudaLaunchAttribute at[1];
        at[0].id = cudaLaunchAttributeClusterDimension;
        at[0].val.clusterDim.x = 8;
        at[0].val.clusterDim.y = 1;
        at[0].val.clusterDim.z = 1;
        cfg.attrs = at;
        cfg.numAttrs = 1;
        cudaLaunchKernelEx(&cfg, k_lstm_t<8>, Whh_f, Whh_b);
    }

    k_feats<<<S_LEN, 384>>>(W_tag, b_tag);
    k_crf1<<<CRF_NCHUNK, 144>>>(trans);
    k_crf2<<<1, 32>>>(trans, tags, out);
}

// round 6
// speedup vs baseline: 1.2947x; 1.2947x over previous
#include <cuda_runtime.h>
#include <cuda_bf16.h>
#include <cooperative_groups.h>
#include <math.h>
#include <cstdint>

namespace cg = cooperative_groups;

// Problem constants
#define S_LEN 4096
#define E_DIM 300
#define H_DIM 256
#define L_CH 32
#define NC 64
#define CE 25
#define CO 25
#define T_TAGS 12
#define START_TAG 10
#define STOP_TAG 11
#define EIN 325          // E + CO
#define G4H 1024         // 4*H
#define CRF_CHUNK 32
#define CRF_NCHUNK (S_LEN / CRF_CHUNK)   // 128

// ---------------- scratch (static device memory; no allocation) --------------
__device__ float g_embeds[S_LEN * EIN];
__device__ float g_X[2][S_LEN * G4H];
__device__ float g_hs[S_LEN * 2 * H_DIM];
__device__ float g_feats[S_LEN * T_TAGS];
__device__ float g_chunkM[CRF_NCHUNK * T_TAGS * T_TAGS];

// ---------------- small PTX helpers ------------------------------------------
__device__ __forceinline__ uint32_t s2u(const void* p) {
    uint32_t a;
    asm("{ .reg .u64 t; cvta.to.shared.u64 t, %1; cvt.u32.u64 %0, t; }"
        : "=r"(a) : "l"(p));
    return a;
}
__device__ __forceinline__ uint32_t mapa_rank(uint32_t a, uint32_t rk) {
    uint32_t d;
    asm("mapa.shared::cluster.u32 %0, %1, %2;" : "=r"(d) : "r"(a), "r"(rk));
    return d;
}
__device__ __forceinline__ void mbar_init(uint32_t a, uint32_t cnt) {
    asm volatile("mbarrier.init.shared.b64 [%0], %1;" :: "r"(a), "r"(cnt) : "memory");
}
__device__ __forceinline__ void mbar_expect(uint32_t a, uint32_t bytes) {
    asm volatile("mbarrier.arrive.expect_tx.shared.b64 _, [%0], %1;"
                 :: "r"(a), "r"(bytes) : "memory");
}
// CTA-scope acquire: st.async data lands in OUR smem, ordered by the local
// mbarrier tx-complete; cluster-scope acquire would emit CCTL.IVALL per poll.
__device__ __forceinline__ void mbar_wait(uint32_t a, uint32_t parity) {
    asm volatile(
        "{\n\t"
        ".reg .pred P;\n\t"
        "W_%=:\n\t"
        "mbarrier.try_wait.parity.acquire.cta.shared::cta.b64 P, [%0], %1, 0x989680;\n\t"
        "@!P bra W_%=;\n\t"
        "}"
        :: "r"(a), "r"(parity) : "memory");
}
// 16-byte vector remote store: 4x fewer DSMEM messages than scalar.
__device__ __forceinline__ void st_async_v4(uint32_t dst, uint32_t v0, uint32_t v1,
                                            uint32_t v2, uint32_t v3, uint32_t mbar) {
    asm volatile(
        "st.async.shared::cluster.mbarrier::complete_tx::bytes.v4.b32 "
        "[%0], {%1, %2, %3, %4}, [%5];"
        :: "r"(dst), "r"(v0), "r"(v1), "r"(v2), "r"(v3), "r"(mbar) : "memory");
}
__device__ __forceinline__ void fma2(unsigned long long& d,
                                     unsigned long long a, unsigned long long b) {
    asm("fma.rn.f32x2 %0, %1, %2, %0;" : "+l"(d) : "l"(a), "l"(b));
}
__device__ __forceinline__ float sum2(unsigned long long v) {
    return __uint_as_float((uint32_t)v) + __uint_as_float((uint32_t)(v >> 32));
}
__device__ __forceinline__ float fsig(float x) {
    return __fdividef(1.f, 1.f + __expf(-x));
}
__device__ __forceinline__ float ftanh(float x) {
    return 1.f - __fdividef(2.f, __expf(2.f * x) + 1.f);
}

// =============================================================================
// K1: char CNN + word-embedding gather -> g_embeds
// =============================================================================
__global__ void k_embed(const int* __restrict__ sentence,
                        const int* __restrict__ chars,
                        const float* __restrict__ word_embed,
                        const float* __restrict__ char_embed,
                        const float* __restrict__ conv_w,
                        const float* __restrict__ conv_b)
{
    int s = blockIdx.x;
    int tid = threadIdx.x;                 // 256 threads

    __shared__ float ce[36 * CE];
    __shared__ float swc[CO * 75];
    __shared__ float swb[CO];
    __shared__ float cv[CO * 34];

    for (int i = tid; i < 36 * CE; i += 256) ce[i] = 0.f;
    for (int i = tid; i < CO * 75; i += 256) swc[i] = conv_w[i];
    if (tid < CO) swb[tid] = conv_b[tid];
    __syncthreads();

    for (int i = tid; i < L_CH * CE; i += 256) {
        int l = i / CE, c = i % CE;
        ce[(l + 2) * CE + c] = char_embed[chars[s * L_CH + l] * CE + c];
    }
    __syncthreads();

    for (int i = tid; i < CO * 34; i += 256) {
        int o = i / 34, tpos = i % 34;
        float acc = swb[o];
        #pragma unroll
        for (int kh = 0; kh < 3; kh++) {
            const float* cer = &ce[(tpos + kh) * CE];
            const float* wr  = &swc[o * 75 + kh * CE];
            #pragma unroll
            for (int c = 0; c < CE; c++) acc = fmaf(cer[c], wr[c], acc);
        }
        cv[o * 34 + tpos] = acc;
    }
    __syncthreads();

    const float* we = word_embed + (size_t)sentence[s] * E_DIM;
    float* erow = g_embeds + (size_t)s * EIN;
    for (int i = tid; i < E_DIM; i += 256) erow[i] = we[i];

    if (tid < CO) {
        float m = cv[tid * 34];
        #pragma unroll
        for (int t = 1; t < 34; t++) m = fmaxf(m, cv[tid * 34 + t]);
        erow[E_DIM + tid] = m;
    }
}

// =============================================================================
// K2: X[d] = embeds @ Wih_d^T + b_d     ([4096,325] x [325,1024])
// =============================================================================
__global__ void k_gemm(const float* __restrict__ Wf, const float* __restrict__ bf,
                       const float* __restrict__ Wb, const float* __restrict__ bb)
{
    int d = blockIdx.z;
    const float* W    = d ? Wb : Wf;
    const float* bias = d ? bb : bf;
    float* X = g_X[d];
    const float* A = g_embeds;

    int m0 = blockIdx.y * 64;
    int n0 = blockIdx.x * 64;

    __shared__ float As[16][65];
    __shared__ float Bs[16][65];

    int tx = threadIdx.x & 15;
    int ty = threadIdx.x >> 4;

    float c[4][4] = {};

    for (int k0 = 0; k0 < EIN; k0 += 16) {
        #pragma unroll
        for (int l = 0; l < 4; l++) {
            int idx = threadIdx.x + l * 256;
            int kk = idx & 15, ml = idx >> 4;
            int k = k0 + kk;
            As[kk][ml] = (k < EIN) ? A[(size_t)(m0 + ml) * EIN + k] : 0.f;
            Bs[kk][ml] = (k < EIN) ? W[(size_t)(n0 + ml) * EIN + k] : 0.f;
        }
        __syncthreads();
        #pragma unroll
        for (int kk = 0; kk < 16; kk++) {
            float a[4], b[4];
            #pragma unroll
            for (int i = 0; i < 4; i++) a[i] = As[kk][ty + 16 * i];
            #pragma unroll
            for (int j = 0; j < 4; j++) b[j] = Bs[kk][tx + 16 * j];
            #pragma unroll
            for (int i = 0; i < 4; i++)
                #pragma unroll
                for (int j = 0; j < 4; j++)
                    c[i][j] = fmaf(a[i], b[j], c[i][j]);
        }
        __syncthreads();
    }

    #pragma unroll
    for (int i = 0; i < 4; i++) {
        int m = m0 + ty + 16 * i;
        #pragma unroll
        for (int j = 0; j < 4; j++) {
            int n = n0 + tx + 16 * j;
            X[(size_t)m * G4H + n] = c[i][j] + bias[n];
        }
    }
}

// =============================================================================
// K3a: BiLSTM, cluster 16 (preferred). CTA rank r owns 16 h-elements
// [16r,16r+16) = 64 gate-rows. Quarter-row split: thread t -> q=t>>6, l=t&63,
// gate=l>>4, e=l&15; each thread does a 64-col partial dot (32 weight regs).
// Writer warp: lanes 0-15 compute gates; fan-out is v4-vectorized: each lane
// assembles chunk c=lane&3 (elements 4c..4c+3) via shfl and sends ONE 16B
// st.async to rank (lane>>2) and one to rank (lane>>2)+8 -> 64 msgs/step.
// =============================================================================
__global__ void __launch_bounds__(256, 1)
k_lstm16(const float* __restrict__ Whh_f, const float* __restrict__ Whh_b)
{
    cg::cluster_group cluster = cg::this_cluster();
    int r = cluster.block_rank();          // 0..15
    int d = blockIdx.x >> 4;               // direction

    __shared__ __align__(16) float sh[2][256];   // double-buffered h
    __shared__ float pbuf[256];                  // quarter-row partials [q][64]
    __shared__ __align__(8) unsigned long long mbar[2];

    int t    = threadIdx.x;
    int q    = t >> 6;
    int l    = t & 63;
    int gate = l >> 4;
    int e    = l & 15;

    uint32_t sh_u = s2u(sh);
    uint32_t mb_u = s2u(mbar);

    for (int i = t; i < 512; i += 256) ((float*)sh)[i] = 0.f;
    if (t == 0) {
        mbar_init(mb_u + 0, 1);
        mbar_init(mb_u + 8, 1);
    }
    __syncthreads();
    if (t == 0) {
        mbar_expect(mb_u + 8, 1024);   // consumed at step 1
        mbar_expect(mb_u + 0, 1024);   // consumed at step 2
    }
    __syncthreads();
    cluster.sync();

    uint32_t rsh[16], rmb[16];
    #pragma unroll
    for (int rk = 0; rk < 16; rk++) {
        rsh[rk] = mapa_rank(sh_u, rk);
        rmb[rk] = mapa_rank(mb_u, rk);
    }

    // this thread's 64 weights -> registers (16 x ulonglong2)
    const float* Whh = d ? Whh_b : Whh_f;
    const ulonglong2* wsrc = reinterpret_cast<const ulonglong2*>(
        Whh + (size_t)(gate * 256 + r * 16 + e) * 256 + q * 64);
    ulonglong2 wreg[16];
    #pragma unroll
    for (int i = 0; i < 16; i++) wreg[i] = wsrc[i];

    const float* Xd = g_X[d];
    int tt = d ? (S_LEN - 1) : 0;
    int ds = d ? -1 : 1;
    int gcol = gate * 256 + r * 16 + e;
    float xcur = (q == 0) ? Xd[(size_t)tt * G4H + gcol] : 0.f;

    float cstate = 0.f;
    int p = 0;
    int par0 = 0, par1 = 0;
    int lane = t & 31;

    for (int s = 0; s < S_LEN; s++) {
        if (s > 0) {
            int b = s & 1;
            if (b) { mbar_wait(mb_u + 8, par1); par1 ^= 1; }
            else   { mbar_wait(mb_u + 0, par0); par0 ^= 1; }
            if (t == 0 && s + 2 < S_LEN) mbar_expect(mb_u + b * 8, 1024);
        }

        float xnext = (q == 0 && s + 1 < S_LEN)
                        ? Xd[(size_t)(tt + ds) * G4H + gcol] : 0.f;

        // quarter-row dot: 64 cols from sh[p][q*64 ..]
        const ulonglong2* hv = reinterpret_cast<const ulonglong2*>(&sh[p][q * 64]);
        unsigned long long a0 = 0ull, a1 = 0ull, a2 = 0ull, a3 = 0ull;
        #pragma unroll
        for (int i = 0; i < 16; i += 2) {
            ulonglong2 h2 = hv[i];
            ulonglong2 h3 = hv[i + 1];
            fma2(a0, wreg[i].x, h2.x);
            fma2(a1, wreg[i].y, h2.y);
            fma2(a2, wreg[i + 1].x, h3.x);
            fma2(a3, wreg[i + 1].y, h3.y);
        }
        float dot = (sum2(a0) + sum2(a1)) + (sum2(a2) + sum2(a3));
        pbuf[q * 64 + l] = dot + xcur;      // xcur == 0 for q != 0
        __syncthreads();

        if (t < 32) {
            float h = 0.f;
            if (t < 16) {
                float zi = 0.f, zf = 0.f, zg = 0.f, zo = 0.f;
                #pragma unroll
                for (int qq = 0; qq < 4; qq++) {
                    zi += pbuf[qq * 64 +       t];
                    zf += pbuf[qq * 64 + 16  + t];
                    zg += pbuf[qq * 64 + 32  + t];
                    zo += pbuf[qq * 64 + 48  + t];
                }
                float ig = fsig(zi);
                float fg = fsig(zf);
                float og = fsig(zo);
                float gg = ftanh(zg);
                cstate = fg * cstate + ig * gg;
                h = og * ftanh(cstate);
                g_hs[(size_t)tt * (2 * H_DIM) + d * H_DIM + r * 16 + t] = h;
            }
            if (s + 1 < S_LEN) {
                int c = lane & 3;              // 16B chunk: elements 4c..4c+3
                float v0 = __shfl_sync(0xffffffffu, h, 4 * c + 0);
                float v1 = __shfl_sync(0xffffffffu, h, 4 * c + 1);
                float v2 = __shfl_sync(0xffffffffu, h, 4 * c + 2);
                float v3 = __shfl_sync(0xffffffffu, h, 4 * c + 3);
                uint32_t off   = (uint32_t)((p ^ 1) * 1024 + (r * 16 + 4 * c) * 4);
                uint32_t mboff = ((s + 1) & 1) * 8;
                int rk0 = lane >> 2;           // 0..7
                st_async_v4(rsh[rk0] + off,
                            __float_as_uint(v0), __float_as_uint(v1),
                            __float_as_uint(v2), __float_as_uint(v3),
                            rmb[rk0] + mboff);
                st_async_v4(rsh[rk0 + 8] + off,
                            __float_as_uint(v0), __float_as_uint(v1),
                            __float_as_uint(v2), __float_as_uint(v3),
                            rmb[rk0 + 8] + mboff);
            }
        }
        p ^= 1;
        tt += ds;
        xcur = xnext;
    }

    cluster.sync();
}

// =============================================================================
// K3b: BiLSTM, cluster 8 fallback (R3/R4 proven structure, v4 fan-out).
// =============================================================================
__global__ void __cluster_dims__(8, 1, 1) __launch_bounds__(256, 1)
k_lstm8(const float* __restrict__ Whh_f, const float* __restrict__ Whh_b)
{
    cg::cluster_group cluster = cg::this_cluster();
    int r = cluster.block_rank();          // 0..7
    int d = blockIdx.x >> 3;               // direction

    __shared__ __align__(16) float sh[2][256];
    __shared__ float pbuf[256];
    __shared__ __align__(8) unsigned long long mbar[2];

    int t    = threadIdx.x;
    int half = t >> 7;
    int l    = t & 127;
    int gate = l >> 5;
    int lane = l & 31;

    uint32_t sh_u = s2u(sh);
    uint32_t mb_u = s2u(mbar);

    for (int i = t; i < 512; i += 256) ((float*)sh)[i] = 0.f;
    if (t == 0) {
        mbar_init(mb_u + 0, 1);
        mbar_init(mb_u + 8, 1);
    }
    __syncthreads();
    if (t == 0) {
        mbar_expect(mb_u + 8, 1024);
        mbar_expect(mb_u + 0, 1024);
    }
    __syncthreads();
    cluster.sync();

    uint32_t rsh[8], rmb[8];
    #pragma unroll
    for (int rk = 0; rk < 8; rk++) {
        rsh[rk] = mapa_rank(sh_u, rk);
        rmb[rk] = mapa_rank(mb_u, rk);
    }

    const float* Whh = d ? Whh_b : Whh_f;
    const ulonglong2* wsrc = reinterpret_cast<const ulonglong2*>(
        Whh + (size_t)(gate * 256 + r * 32 + lane) * 256 + half * 128);
    ulonglong2 wreg[32];
    #pragma unroll
    for (int i = 0; i < 32; i++) wreg[i] = wsrc[i];

    const float* Xd = g_X[d];
    int tt = d ? (S_LEN - 1) : 0;
    int ds = d ? -1 : 1;
    int gcol = gate * 256 + r * 32 + lane;
    float xcur = (half == 0) ? Xd[(size_t)tt * G4H + gcol] : 0.f;

    float cstate = 0.f;
    int p = 0;
    int par0 = 0, par1 = 0;

    for (int s = 0; s < S_LEN; s++) {
        if (s > 0) {
            int b = s & 1;
            if (b) { mbar_wait(mb_u + 8, par1); par1 ^= 1; }
            else   { mbar_wait(mb_u + 0, par0); par0 ^= 1; }
            if (t == 0 && s + 2 < S_LEN) mbar_expect(mb_u + b * 8, 1024);
        }

        float xnext = (half == 0 && s + 1 < S_LEN)
                        ? Xd[(size_t)(tt + ds) * G4H + gcol] : 0.f;

        const ulonglong2* hv = reinterpret_cast<const ulonglong2*>(&sh[p][half * 128]);
        unsigned long long a0 = 0ull, a1 = 0ull, a2 = 0ull, a3 = 0ull;
        #pragma unroll
        for (int i = 0; i < 32; i += 2) {
            ulonglong2 h2 = hv[i];
            ulonglong2 h3 = hv[i + 1];
            fma2(a0, wreg[i].x, h2.x);
            fma2(a1, wreg[i].y, h2.y);
            fma2(a2, wreg[i + 1].x, h3.x);
            fma2(a3, wreg[i + 1].y, h3.y);
        }
        float dot = (sum2(a0) + sum2(a1)) + (sum2(a2) + sum2(a3));
        pbuf[t] = dot + xcur;
        __syncthreads();

        if (t < 32) {
            float zi = pbuf[t]       + pbuf[128 + t];
            float zf = pbuf[32 + t]  + pbuf[160 + t];
            float zg = pbuf[64 + t]  + pbuf[192 + t];
            float zo = pbuf[96 + t]  + pbuf[224 + t];
            float ig = fsig(zi);
            float fg = fsig(zf);
            float og = fsig(zo);
            float gg = ftanh(zg);
            cstate = fg * cstate + ig * gg;
            float h = og * ftanh(cstate);
            g_hs[(size_t)tt * (2 * H_DIM) + d * H_DIM + r * 32 + t] = h;

            if (s + 1 < S_LEN) {
                int c = t & 7;                 // chunk: elements 4c..4c+3
                float v0 = __shfl_sync(0xffffffffu, h, 4 * c + 0);
                float v1 = __shfl_sync(0xffffffffu, h, 4 * c + 1);
                float v2 = __shfl_sync(0xffffffffu, h, 4 * c + 2);
                float v3 = __shfl_sync(0xffffffffu, h, 4 * c + 3);
                uint32_t off   = (uint32_t)((p ^ 1) * 1024 + (r * 32 + 4 * c) * 4);
                uint32_t mboff = ((s + 1) & 1) * 8;
                int rk0 = t >> 3;              // 0..3
                st_async_v4(rsh[rk0] + off,
                            __float_as_uint(v0), __float_as_uint(v1),
                            __float_as_uint(v2), __float_as_uint(v3),
                            rmb[rk0] + mboff);
                st_async_v4(rsh[rk0 + 4] + off,
                            __float_as_uint(v0), __float_as_uint(v1),
                            __float_as_uint(v2), __float_as_uint(v3),
                            rmb[rk0 + 4] + mboff);
            }
        }
        p ^= 1;
        tt += ds;
        xcur = xnext;
    }

    cluster.sync();
}

// =============================================================================
// K4: feats = lstm_out @ W_tag^T + b_tag
// =============================================================================
__global__ void k_feats(const float* __restrict__ W_tag, const float* __restrict__ b_tag)
{
    int s = blockIdx.x;
    int w = threadIdx.x >> 5;
    int lane = threadIdx.x & 31;
    if (w >= T_TAGS) return;

    const float* hrow = g_hs + (size_t)s * (2 * H_DIM);
    const float* wt = W_tag + (size_t)w * (2 * H_DIM);
    float acc = 0.f;
    #pragma unroll 4
    for (int k = lane; k < 2 * H_DIM; k += 32) acc = fmaf(hrow[k], wt[k], acc);
    #pragma unroll
    for (int off = 16; off; off >>= 1) acc += __shfl_down_sync(0xffffffffu, acc, off);
    if (lane == 0) g_feats[s * T_TAGS + w] = acc + b_tag[w];
}

// =============================================================================
// K5a: CRF parallel scan, stage 1.
// =============================================================================
__global__ void k_crf1(const float* __restrict__ trans)
{
    int b = blockIdx.x;
    int tid = threadIdx.x;                 // 144
    int i = tid / T_TAGS, k = tid % T_TAGS;

    __shared__ float cur[T_TAGS][T_TAGS + 1];
    __shared__ float str[T_TAGS * T_TAGS];

    str[tid] = trans[tid];
    __syncthreads();

    float trk[T_TAGS];
    #pragma unroll
    for (int j = 0; j < T_TAGS; j++) trk[j] = str[j * T_TAGS + k];

    int s0 = b * CRF_CHUNK;
    cur[i][k] = str[i * T_TAGS + k] + g_feats[s0 * T_TAGS + k];
    __syncthreads();

    float featn = g_feats[(s0 + 1) * T_TAGS + k];
    for (int s = s0 + 1; s < s0 + CRF_CHUNK; s++) {
        float fcur = featn;
        featn = (s + 1 < s0 + CRF_CHUNK) ? g_feats[(s + 1) * T_TAGS + k] : 0.f;

        float av[T_TAGS];
        float m = -1e30f;
        #pragma unroll
        for (int j = 0; j < T_TAGS; j++) {
            av[j] = cur[i][j] + trk[j];
            m = fmaxf(m, av[j]);
        }
        float sum = 0.f;
        #pragma unroll
        for (int j = 0; j < T_TAGS; j++) sum += __expf(av[j] - m);
        float nv = fcur + m + __logf(sum);
        __syncthreads();
        cur[i][k] = nv;
        __syncthreads();
    }
    g_chunkM[b * 144 + i * T_TAGS + k] = cur[i][k];
}

// =============================================================================
// K5b: CRF stage 2 — fold chunk matrices, terminal LSE, gold.
// =============================================================================
__global__ void k_crf2(const float* __restrict__ trans,
                       const int* __restrict__ tags,
                       float* __restrict__ out)
{
    int lane = threadIdx.x;                // 32 threads
    int j = (lane < T_TAGS) ? lane : 0;

    float alpha = (lane == START_TAG) ? 0.f : -10000.f;

    for (int b = 0; b < CRF_NCHUNK; b++) {
        const float* M = g_chunkM + b * 144;
        float mv[T_TAGS];
        #pragma unroll
        for (int i = 0; i < T_TAGS; i++) mv[i] = M[i * T_TAGS + j];
        float av[T_TAGS];
        float m = -1e30f;
        #pragma unroll
        for (int i = 0; i < T_TAGS; i++) {
            av[i] = __shfl_sync(0xffffffffu, alpha, i) + mv[i];
            m = fmaxf(m, av[i]);
        }
        float sum = 0.f;
        #pragma unroll
        for (int i = 0; i < T_TAGS; i++) sum += __expf(av[i] - m);
        alpha = m + __logf(sum);
    }

    float term = alpha + trans[j * T_TAGS + STOP_TAG];
    float m = -1e30f;
    #pragma unroll
    for (int i = 0; i < T_TAGS; i++)
        m = fmaxf(m, __shfl_sync(0xffffffffu, term, i));
    float sum = 0.f;
    #pragma unroll
    for (int i = 0; i < T_TAGS; i++)
        sum += __expf(__shfl_sync(0xffffffffu, term, i) - m);
    float fwd = m + __logf(sum);

    float g = 0.f;
    for (int s = lane; s < S_LEN; s += 32) {
        int tcur = tags[s];
        int tprev = s ? tags[s - 1] : START_TAG;
        g += trans[tprev * T_TAGS + tcur] + g_feats[s * T_TAGS + tcur];
    }
    #pragma unroll
    for (int off = 16; off; off >>= 1) g += __shfl_down_sync(0xffffffffu, g, off);

    if (lane == 0) {
        g += trans[tags[S_LEN - 1] * T_TAGS + STOP_TAG];
        out[0] = fwd - g;
    }
}

// =============================================================================
// launch
// =============================================================================
extern "C" void kernel_launch(void* const* d_in, const int* in_sizes, int n_in,
                              void* d_out, int out_size)
{
    const int*   sentence   = (const int*)  d_in[0];
    const int*   chars      = (const int*)  d_in[1];
    const int*   tags       = (const int*)  d_in[2];
    const float* word_embed = (const float*)d_in[4];
    const float* char_embed = (const float*)d_in[5];
    const float* conv_w     = (const float*)d_in[6];
    const float* conv_b     = (const float*)d_in[7];
    const float* Wih_f      = (const float*)d_in[8];
    const float* Whh_f      = (const float*)d_in[9];
    const float* b_f        = (const float*)d_in[10];
    const float* Wih_b      = (const float*)d_in[11];
    const float* Whh_b      = (const float*)d_in[12];
    const float* b_b        = (const float*)d_in[13];
    const float* W_tag      = (const float*)d_in[14];
    const float* b_tag      = (const float*)d_in[15];
    const float* trans      = (const float*)d_in[16];
    float* out = (float*)d_out;

    k_embed<<<S_LEN, 256>>>(sentence, chars, word_embed, char_embed, conv_w, conv_b);
    k_gemm<<<dim3(G4H / 64, S_LEN / 64, 2), 256>>>(Wih_f, b_f, Wih_b, b_b);

    // Prefer cluster-16 (non-portable); fall back to proven cluster-8 kernel.
    bool use16 = false;
    {
        cudaFuncSetAttribute(k_lstm16,
                             cudaFuncAttributeNonPortableClusterSizeAllowed, 1);
        cudaLaunchConfig_t cfg = {};
        cfg.gridDim  = dim3(32, 1, 1);
        cfg.blockDim = dim3(256, 1, 1);
        cudaLaunchAttribute at[1];
        at[0].id = cudaLaunchAttributeClusterDimension;
        at[0].val.clusterDim.x = 16;
        at[0].val.clusterDim.y = 1;
        at[0].val.clusterDim.z = 1;
        cfg.attrs = at;
        cfg.numAttrs = 1;
        int nclus = 0;
        cudaError_t qe = cudaOccupancyMaxActiveClusters(&nclus, k_lstm16, &cfg);
        if (qe == cudaSuccess && nclus >= 2) {
            cudaError_t le = cudaLaunchKernelEx(&cfg, k_lstm16, Whh_f, Whh_b);
            use16 = (le == cudaSuccess);
        }
        if (!use16) cudaGetLastError();   // clear any sticky error
    }
    if (!use16)
        k_lstm8<<<16, 256>>>(Whh_f, Whh_b);

    k_feats<<<S_LEN, 384>>>(W_tag, b_tag);
    k_crf1<<<CRF_NCHUNK, 144>>>(trans);
    k_crf2<<<1, 32>>>(trans, tags, out);
}